// round 1
// baseline (speedup 1.0000x reference)
#include <cuda_runtime.h>
#include <math.h>

// Problem constants
#define Bq   1024
#define Kn   200
#define Dd   128
#define D2   256
#define G8   1024      // 8*D
#define NG   896       // gate columns actually needed (skip o[:,128:256])
#define STEPS 4

// ---------------- device scratch (no allocations allowed) ----------------
__device__ float g_csum  [Bq * D2];        // sum over neighbors of [rel|ent]
__device__ float g_support[Bq * Dd];
__device__ float g_hidden[Bq * D2];
__device__ float g_sg    [Bq * Dd];        // support_g (pre-LN then in-place LN)
__device__ float g_q     [Bq * Dd];
__device__ float g_gq    [Bq * G8];        // q@w_ih^T + b_ih + b_hh (ld=1024)
__device__ float g_gates [Bq * G8];        // ld=1024, only first 896 cols valid
__device__ float g_hr    [Bq * D2];        // [h_out | r]
__device__ float g_c     [Bq * D2];
__device__ float g_hout  [Bq * Dd];
__device__ float g_logits[Bq * Bq];
__device__ float g_rpart [4 * Bq * Dd];    // split-K partials for r

// ---------------- helpers ----------------
__device__ __forceinline__ float sigm(float x) { return 1.0f / (1.0f + expf(-x)); }

__device__ __forceinline__ float bsum(float v, float* sm, int nw) {
    #pragma unroll
    for (int o = 16; o; o >>= 1) v += __shfl_xor_sync(0xffffffffu, v, o);
    int w = threadIdx.x >> 5;
    __syncthreads();
    if ((threadIdx.x & 31) == 0) sm[w] = v;
    __syncthreads();
    float r = 0.f;
    for (int i = 0; i < nw; i++) r += sm[i];
    return r;
}

// ---------------- K1: neighbor gather + sum ----------------
// one block per b; warps 0-3 sum rel rows, warps 4-7 sum ent rows
__global__ __launch_bounds__(256) void gather_sum_kernel(
    const int* __restrict__ rel, const int* __restrict__ ent,
    const float* __restrict__ emb, float* __restrict__ csum)
{
    int b = blockIdx.x;
    int tid = threadIdx.x;
    int warp = tid >> 5, lane = tid & 31;

    __shared__ int sidx[2 * Kn];
    for (int i = tid; i < 2 * Kn; i += 256)
        sidx[i] = (i < Kn) ? rel[b * Kn + i] : ent[b * Kn + (i - Kn)];
    __syncthreads();

    int side = warp >> 2;       // 0 = rel, 1 = ent
    int w    = warp & 3;
    const int* idxs = sidx + side * Kn;

    float4 acc = make_float4(0.f, 0.f, 0.f, 0.f);
    #pragma unroll 4
    for (int k = w; k < Kn; k += 4) {
        int row = idxs[k];
        float4 v = *reinterpret_cast<const float4*>(emb + (size_t)row * Dd + lane * 4);
        acc.x += v.x; acc.y += v.y; acc.z += v.z; acc.w += v.w;
    }

    __shared__ float4 red[8][32];
    red[warp][lane] = acc;
    __syncthreads();
    if ((warp & 3) == 0) {
        float4 s  = red[warp][lane];
        float4 s1 = red[warp + 1][lane];
        float4 s2 = red[warp + 2][lane];
        float4 s3 = red[warp + 3][lane];
        s.x += s1.x + s2.x + s3.x;
        s.y += s1.y + s2.y + s3.y;
        s.z += s1.z + s2.z + s3.z;
        s.w += s1.w + s2.w + s3.w;
        *reinterpret_cast<float4*>(csum + b * D2 + side * Dd + lane * 4) = s;
    }
}

// ---------------- generic fp32 GEMM, C = A(MxK) @ B(NxK)^T, fused epilogues --------
// modes: 0 c=acc(+b1)  1 tanh((acc+200*b1)/1024)  2 relu(acc+b1)
//        3 acc+b1+add  4 acc+b1+b2  5 acc+add
#define BM 64
#define BN 64
#define BKK 16
__global__ __launch_bounds__(256) void sgemm_tn(
    const float* __restrict__ A, const float* __restrict__ B, float* __restrict__ C,
    int M, int N, int K, int ldc,
    const float* __restrict__ b1, const float* __restrict__ b2,
    const float* __restrict__ add, int ldadd, int mode)
{
    __shared__ float As[BKK][BM + 4];
    __shared__ float Bs[BKK][BN + 4];
    int tid = threadIdx.x;
    int bx = blockIdx.x, by = blockIdx.y;
    int tx = tid & 15, ty = tid >> 4;
    int arow = tid >> 2;            // 0..63
    int acol = (tid & 3) << 2;      // 0,4,8,12

    const float* Ap = A + (size_t)(by * BM + arow) * K + acol;
    const float* Bp = B + (size_t)(bx * BN + arow) * K + acol;

    float acc[4][4];
    #pragma unroll
    for (int i = 0; i < 4; i++)
        #pragma unroll
        for (int j = 0; j < 4; j++) acc[i][j] = 0.f;

    for (int k0 = 0; k0 < K; k0 += BKK) {
        float4 a4 = *reinterpret_cast<const float4*>(Ap + k0);
        float4 b4 = *reinterpret_cast<const float4*>(Bp + k0);
        As[acol + 0][arow] = a4.x; As[acol + 1][arow] = a4.y;
        As[acol + 2][arow] = a4.z; As[acol + 3][arow] = a4.w;
        Bs[acol + 0][arow] = b4.x; Bs[acol + 1][arow] = b4.y;
        Bs[acol + 2][arow] = b4.z; Bs[acol + 3][arow] = b4.w;
        __syncthreads();
        #pragma unroll
        for (int k = 0; k < BKK; k++) {
            float4 av = *reinterpret_cast<const float4*>(&As[k][ty << 2]);
            float4 bv = *reinterpret_cast<const float4*>(&Bs[k][tx << 2]);
            acc[0][0] += av.x * bv.x; acc[0][1] += av.x * bv.y; acc[0][2] += av.x * bv.z; acc[0][3] += av.x * bv.w;
            acc[1][0] += av.y * bv.x; acc[1][1] += av.y * bv.y; acc[1][2] += av.y * bv.z; acc[1][3] += av.y * bv.w;
            acc[2][0] += av.z * bv.x; acc[2][1] += av.z * bv.y; acc[2][2] += av.z * bv.z; acc[2][3] += av.z * bv.w;
            acc[3][0] += av.w * bv.x; acc[3][1] += av.w * bv.y; acc[3][2] += av.w * bv.z; acc[3][3] += av.w * bv.w;
        }
        __syncthreads();
    }

    int m0 = by * BM + (ty << 2);
    int n0 = bx * BN + (tx << 2);
    #pragma unroll
    for (int i = 0; i < 4; i++) {
        float vals[4];
        #pragma unroll
        for (int j = 0; j < 4; j++) {
            float v = acc[i][j];
            int n = n0 + j;
            if (mode == 0)      { if (b1) v += b1[n]; }
            else if (mode == 1) { v = tanhf((v + 200.0f * b1[n]) * (1.0f / 1024.0f)); }
            else if (mode == 2) { v = fmaxf(v + b1[n], 0.f); }
            else if (mode == 3) { v += b1[n] + add[(size_t)(m0 + i) * ldadd + n]; }
            else if (mode == 4) { v += b1[n] + b2[n]; }
            else                { v += add[(size_t)(m0 + i) * ldadd + n]; }
            vals[j] = v;
        }
        *reinterpret_cast<float4*>(&C[(size_t)(m0 + i) * ldc + n0]) =
            make_float4(vals[0], vals[1], vals[2], vals[3]);
    }
}

// ---------------- NN GEMM with split-K: Cpart[z] = A[:,kz] @ B[kz,:] ----------------
__global__ __launch_bounds__(256) void sgemm_nn_splitk(
    const float* __restrict__ A, const float* __restrict__ B, float* __restrict__ Cpart,
    int M, int N, int K, int ldb, int kchunk)
{
    __shared__ float As[BKK][BM + 4];
    __shared__ float Bs[BKK][BN];
    int tid = threadIdx.x;
    int bx = blockIdx.x, by = blockIdx.y;
    int kbeg = blockIdx.z * kchunk;
    int tx = tid & 15, ty = tid >> 4;
    int arow = tid >> 2;
    int acol = (tid & 3) << 2;
    int bk   = tid >> 4;            // 0..15
    int bn   = (tid & 15) << 2;     // 0..60

    const float* Ap = A + (size_t)(by * BM + arow) * K + kbeg + acol;
    const float* Bp = B + (size_t)(kbeg + bk) * ldb + bx * BN + bn;

    float acc[4][4];
    #pragma unroll
    for (int i = 0; i < 4; i++)
        #pragma unroll
        for (int j = 0; j < 4; j++) acc[i][j] = 0.f;

    for (int k0 = 0; k0 < kchunk; k0 += BKK) {
        float4 a4 = *reinterpret_cast<const float4*>(Ap + k0);
        float4 b4 = *reinterpret_cast<const float4*>(Bp + (size_t)k0 * ldb);
        As[acol + 0][arow] = a4.x; As[acol + 1][arow] = a4.y;
        As[acol + 2][arow] = a4.z; As[acol + 3][arow] = a4.w;
        *reinterpret_cast<float4*>(&Bs[bk][bn]) = b4;
        __syncthreads();
        #pragma unroll
        for (int k = 0; k < BKK; k++) {
            float4 av = *reinterpret_cast<const float4*>(&As[k][ty << 2]);
            float4 bv = *reinterpret_cast<const float4*>(&Bs[k][tx << 2]);
            acc[0][0] += av.x * bv.x; acc[0][1] += av.x * bv.y; acc[0][2] += av.x * bv.z; acc[0][3] += av.x * bv.w;
            acc[1][0] += av.y * bv.x; acc[1][1] += av.y * bv.y; acc[1][2] += av.y * bv.z; acc[1][3] += av.y * bv.w;
            acc[2][0] += av.z * bv.x; acc[2][1] += av.z * bv.y; acc[2][2] += av.z * bv.z; acc[2][3] += av.z * bv.w;
            acc[3][0] += av.w * bv.x; acc[3][1] += av.w * bv.y; acc[3][2] += av.w * bv.z; acc[3][3] += av.w * bv.w;
        }
        __syncthreads();
    }

    int m0 = by * BM + (ty << 2);
    int n0 = bx * BN + (tx << 2);
    float* Cz = Cpart + (size_t)blockIdx.z * M * N;
    #pragma unroll
    for (int i = 0; i < 4; i++)
        *reinterpret_cast<float4*>(&Cz[(size_t)(m0 + i) * N + n0]) =
            make_float4(acc[i][0], acc[i][1], acc[i][2], acc[i][3]);
}

// reduce split-K partials of r into g_hr[:,128:256]
__global__ __launch_bounds__(256) void reduce_r_kernel(const float* __restrict__ part,
                                                       float* __restrict__ hr)
{
    int idx = blockIdx.x * 256 + threadIdx.x;   // 0 .. Bq*Dd
    int b = idx >> 7, d = idx & 127;
    float s = part[idx] + part[Bq * Dd + idx] + part[2 * Bq * Dd + idx] + part[3 * Bq * Dd + idx];
    hr[b * D2 + Dd + d] = s;
}

// ---------------- layernorm (unbiased std, eps added to std) ----------------
__global__ __launch_bounds__(128) void layernorm_kernel(float* __restrict__ Z,
                                                        const float* __restrict__ a,
                                                        const float* __restrict__ b)
{
    __shared__ float sm[4];
    int row = blockIdx.x, t = threadIdx.x;
    float z = Z[row * Dd + t];
    float mu = bsum(z, sm, 4) * (1.0f / Dd);
    float d = z - mu;
    float var = bsum(d * d, sm, 4) * (1.0f / (Dd - 1));
    float sig = sqrtf(var);
    Z[row * Dd + t] = d / (sig + 1e-3f) * a[t] + b[t];
}

// ---------------- q gather ----------------
__global__ __launch_bounds__(256) void gather_q_kernel(const int* __restrict__ qry,
                                                       const float* __restrict__ emb,
                                                       float* __restrict__ q)
{
    int idx = blockIdx.x * 256 + threadIdx.x;
    int b = idx >> 7, d = idx & 127;
    q[idx] = emb[(size_t)qry[b] * Dd + d];
}

// ---------------- LSTM elementwise ----------------
__global__ __launch_bounds__(256) void lstm_ew_kernel(const float* __restrict__ gates,
                                                      const float* __restrict__ q,
                                                      float* __restrict__ c,
                                                      float* __restrict__ hout,
                                                      float* __restrict__ hr,
                                                      int first)
{
    int b = blockIdx.x, t = threadIdx.x;
    const float* g = gates + (size_t)b * G8;
    float ig = g[t];
    float fg = g[D2 + t];
    float gg = g[2 * D2 + t];
    float cprev = first ? 0.f : c[b * D2 + t];
    float cn = sigm(fg) * cprev + sigm(ig) * tanhf(gg);
    c[b * D2 + t] = cn;
    if (t < Dd) {
        float og = g[3 * D2 + t];
        float h  = sigm(og) * tanhf(cn);
        float ho = q[b * Dd + t] + h;
        hout[b * Dd + t] = ho;
        hr[b * D2 + t]   = ho;
    }
}

// ---------------- row softmax over 1024 ----------------
__global__ __launch_bounds__(256) void softmax_kernel(float* __restrict__ P)
{
    __shared__ float sm[8];
    __shared__ float ss[8];
    int row = blockIdx.x, t = threadIdx.x;
    float* p = P + (size_t)row * Bq;
    float4 v = *reinterpret_cast<const float4*>(p + t * 4);
    float m = fmaxf(fmaxf(v.x, v.y), fmaxf(v.z, v.w));
    #pragma unroll
    for (int o = 16; o; o >>= 1) m = fmaxf(m, __shfl_xor_sync(0xffffffffu, m, o));
    if ((t & 31) == 0) sm[t >> 5] = m;
    __syncthreads();
    float M = sm[0];
    #pragma unroll
    for (int i = 1; i < 8; i++) M = fmaxf(M, sm[i]);
    float e0 = expf(v.x - M), e1 = expf(v.y - M), e2 = expf(v.z - M), e3 = expf(v.w - M);
    float s = e0 + e1 + e2 + e3;
    #pragma unroll
    for (int o = 16; o; o >>= 1) s += __shfl_xor_sync(0xffffffffu, s, o);
    if ((t & 31) == 0) ss[t >> 5] = s;
    __syncthreads();
    float S = 0.f;
    #pragma unroll
    for (int i = 0; i < 8; i++) S += ss[i];
    float inv = 1.0f / S;
    *reinterpret_cast<float4*>(p + t * 4) = make_float4(e0 * inv, e1 * inv, e2 * inv, e3 * inv);
}

// ---------------- final cosine similarity ----------------
__global__ __launch_bounds__(128) void cosine_kernel(const float* __restrict__ H,
                                                     const float* __restrict__ G,
                                                     float* __restrict__ out)
{
    __shared__ float sm[4];
    int row = blockIdx.x, t = threadIdx.x;
    float h = H[row * Dd + t];
    float g = G[row * Dd + t];
    float s1 = bsum(h * g, sm, 4);
    float s2 = bsum(h * h, sm, 4);
    float s3 = bsum(g * g, sm, 4);
    if (t == 0) out[row] = s1 / sqrtf(s2 * s3);
}

// ---------------- launcher ----------------
extern "C" void kernel_launch(void* const* d_in, const int* in_sizes, int n_in,
                              void* d_out, int out_size)
{
    const int*   rel = (const int*)d_in[0];
    const int*   ent = (const int*)d_in[1];
    const int*   qry = (const int*)d_in[2];
    const float* emb = (const float*)d_in[3];
    const float* Wg  = (const float*)d_in[4];
    const float* bg  = (const float*)d_in[5];
    const float* p1w = (const float*)d_in[6];
    const float* p1b = (const float*)d_in[7];
    const float* p2w = (const float*)d_in[8];
    const float* p2b = (const float*)d_in[9];
    const float* lna = (const float*)d_in[10];
    const float* lnb = (const float*)d_in[11];
    const float* wih = (const float*)d_in[12];
    const float* whh = (const float*)d_in[13];
    const float* bih = (const float*)d_in[14];
    const float* bhh = (const float*)d_in[15];
    float* out = (float*)d_out;

    float *csum, *support, *hidden, *sg, *q, *gq, *gates, *hr, *c, *hout, *logits, *rpart;
    cudaGetSymbolAddress((void**)&csum,   g_csum);
    cudaGetSymbolAddress((void**)&support,g_support);
    cudaGetSymbolAddress((void**)&hidden, g_hidden);
    cudaGetSymbolAddress((void**)&sg,     g_sg);
    cudaGetSymbolAddress((void**)&q,      g_q);
    cudaGetSymbolAddress((void**)&gq,     g_gq);
    cudaGetSymbolAddress((void**)&gates,  g_gates);
    cudaGetSymbolAddress((void**)&hr,     g_hr);
    cudaGetSymbolAddress((void**)&c,      g_c);
    cudaGetSymbolAddress((void**)&hout,   g_hout);
    cudaGetSymbolAddress((void**)&logits, g_logits);
    cudaGetSymbolAddress((void**)&rpart,  g_rpart);

    // 1) neighbor gather-sum
    gather_sum_kernel<<<Bq, 256>>>(rel, ent, emb, csum);

    // 2) support = tanh((csum @ Wg^T + 200*bg) / 1024)
    sgemm_tn<<<dim3(Dd / BN, Bq / BM), 256>>>(csum, Wg, support, Bq, Dd, D2, Dd,
                                              bg, nullptr, nullptr, 0, 1);
    // 3) hidden = relu(support @ p1w^T + p1b)
    sgemm_tn<<<dim3(D2 / BN, Bq / BM), 256>>>(support, p1w, hidden, Bq, D2, Dd, D2,
                                              p1b, nullptr, nullptr, 0, 2);
    // 4) sg = hidden @ p2w^T + p2b + support ; then layernorm in-place
    sgemm_tn<<<dim3(Dd / BN, Bq / BM), 256>>>(hidden, p2w, sg, Bq, Dd, D2, Dd,
                                              p2b, nullptr, support, Dd, 3);
    layernorm_kernel<<<Bq, 128>>>(sg, lna, lnb);

    // 5) q gather ; gq = q @ wih^T + bih + bhh  (only 896 gate cols needed)
    gather_q_kernel<<<Bq * Dd / 256, 256>>>(qry, emb, q);
    sgemm_tn<<<dim3(NG / BN, Bq / BM), 256>>>(q, wih, gq, Bq, NG, Dd, G8,
                                              bih, bhh, nullptr, 0, 4);

    // 6) LSTM + attention loop
    for (int s = 0; s < STEPS; s++) {
        const float* gsrc = gq;
        if (s > 0) {
            sgemm_tn<<<dim3(NG / BN, Bq / BM), 256>>>(hr, whh, gates, Bq, NG, D2, G8,
                                                      nullptr, nullptr, gq, G8, 5);
            gsrc = gates;
        }
        lstm_ew_kernel<<<Bq, 256>>>(gsrc, q, c, hout, hr, s == 0 ? 1 : 0);

        // logits = hout @ sg^T ; softmax rows
        sgemm_tn<<<dim3(Bq / BN, Bq / BM), 256>>>(hout, sg, logits, Bq, Bq, Dd, Bq,
                                                  nullptr, nullptr, nullptr, 0, 0);
        softmax_kernel<<<Bq, 256>>>(logits);

        // r = P @ sg  (split-K over 1024), write into hr[:,128:256]
        sgemm_nn_splitk<<<dim3(Dd / BN, Bq / BM, 4), 256>>>(logits, sg, rpart,
                                                            Bq, Dd, Bq, Dd, 256);
        reduce_r_kernel<<<Bq * Dd / 256, 256>>>(rpart, hr);
    }

    // 7) cosine similarity
    cosine_kernel<<<Bq, 128>>>(hout, sg, out);
}

// round 3
// speedup vs baseline: 1.5167x; 1.5167x over previous
#include <cuda_runtime.h>
#include <cuda_bf16.h>
#include <math.h>
#include <stdint.h>

// Problem constants
#define Bq   1024
#define Kn   200
#define Dd   128
#define D2   256
#define G8   1024      // 8*D
#define STEPS 4
#define RSPLIT 4

// ---------------- device scratch ----------------
__device__ float g_csum  [Bq * D2];
__device__ float g_support[Bq * Dd];
__device__ float g_hidden[Bq * D2];
__device__ float g_sg    [Bq * Dd];
__device__ float g_sgT   [Dd * Bq];
__device__ float g_q     [Bq * Dd];
__device__ float g_gq    [Bq * G8];
__device__ float g_gates [Bq * G8];
__device__ float g_hr    [Bq * D2];
__device__ float g_c     [Bq * D2];
__device__ float g_hout  [Bq * Dd];
__device__ float g_logits[Bq * Bq];
__device__ float g_rpart [RSPLIT * Bq * Dd];

// =================== helpers ===================
__device__ __forceinline__ uint32_t smem_u32(const void* p) {
    uint32_t a;
    asm("{ .reg .u64 t; cvta.to.shared.u64 t, %1; cvt.u32.u64 %0, t; }" : "=r"(a) : "l"(p));
    return a;
}

#define LDSM_X4(r0, r1, r2, r3, addr) \
    asm volatile("ldmatrix.sync.aligned.m8n8.x4.shared.b16 {%0,%1,%2,%3}, [%4];" \
        : "=r"(r0), "=r"(r1), "=r"(r2), "=r"(r3) : "r"(addr))

#define MMA_BF16(acc, a, bb0, bb1) \
    asm volatile("mma.sync.aligned.m16n8k16.row.col.f32.bf16.bf16.f32 " \
        "{%0,%1,%2,%3}, {%4,%5,%6,%7}, {%8,%9}, {%0,%1,%2,%3};" \
        : "+f"((acc)[0]), "+f"((acc)[1]), "+f"((acc)[2]), "+f"((acc)[3]) \
        : "r"((a)[0]), "r"((a)[1]), "r"((a)[2]), "r"((a)[3]), "r"(bb0), "r"(bb1))

// split two fp32 into bf16-hi pair + bf16-lo (residual) pair
__device__ __forceinline__ void split2(float x0, float x1, unsigned &h, unsigned &l) {
    __nv_bfloat162 hh = __float22bfloat162_rn(make_float2(x0, x1));
    float2 hf = __bfloat1622float2(hh);
    __nv_bfloat162 ll = __float22bfloat162_rn(make_float2(x0 - hf.x, x1 - hf.y));
    h = *reinterpret_cast<unsigned*>(&hh);
    l = *reinterpret_cast<unsigned*>(&ll);
}

// fused epilogue
__device__ __forceinline__ float epi(float x, int m, int n, int mode,
                                     const float* __restrict__ b1,
                                     const float* __restrict__ b2,
                                     const float* __restrict__ add, int ldadd) {
    if (mode == 1) return tanhf((x + 200.0f * b1[n]) * (1.0f / 1024.0f));
    if (mode == 2) return fmaxf(x + b1[n], 0.0f);
    if (mode == 3) return x + b1[n] + add[(size_t)m * ldadd + n];
    if (mode == 4) return x + b1[n] + b2[n];
    if (mode == 5) return x + add[(size_t)m * ldadd + n];
    return x;
}

// =================== HMMA TN GEMM: C = A(MxK) @ B(NxK)^T, fp32 via bf16x3 =============
// CTA tile 64x64, warps 2x4 (each 32x16), K staged 64 per chunk.
// grid = (N/64, M/64, zsplit); per z: K range [z*kchunk, (z+1)*kchunk)
#define LDS 72            // bf16 elements per smem row (144B: 16B aligned, ldmatrix conflict-free)
#define TILE_ELE (64 * LDS)

__global__ void __launch_bounds__(256, 1)
tgemm(const float* __restrict__ A, int lda,
      const float* __restrict__ B, int ldb,
      float* __restrict__ C, int ldc,
      int kchunk, long zstride,
      const float* __restrict__ b1, const float* __restrict__ b2,
      const float* __restrict__ add, int ldadd, int mode)
{
    __shared__ __nv_bfloat162 sm2[4 * TILE_ELE / 2];   // Ah | Al | Bh | Bl
    const uint32_t sbase = smem_u32(sm2);
    const uint32_t AhB = sbase;
    const uint32_t AlB = sbase + TILE_ELE * 2;
    const uint32_t BhB = sbase + 2 * TILE_ELE * 2;
    const uint32_t BlB = sbase + 3 * TILE_ELE * 2;

    const int tid  = threadIdx.x;
    const int lane = tid & 31;
    const int wid  = tid >> 5;
    const int wy   = wid >> 2;           // 0..1  (rows of 32)
    const int wx   = wid & 3;            // 0..3  (cols of 16)
    const int m0 = blockIdx.y * 64;
    const int n0 = blockIdx.x * 64;
    const int kbeg = blockIdx.z * kchunk;
    C += (long)blockIdx.z * zstride;

    // loader indexing: row = tid/4 (0..63), col-quad = tid%4 (16 cols each)
    const int lr = tid >> 2;
    const int lc = (tid & 3) * 16;

    // ldmatrix source addresses (byte offsets within tile)
    // A frag: rows m = lane&15 (+ mi*16), k-half = (lane>>4)*8
    const uint32_t aOff = (uint32_t)(((wy * 32 + (lane & 15)) * LDS + (lane >> 4) * 8) * 2);
    // B frag: group g=lane>>3: n_off=(g>>1)*8, k_off=(g&1)*8, row=lane&7
    const int bg = lane >> 3;
    const uint32_t bOff = (uint32_t)(((wx * 16 + (bg >> 1) * 8 + (lane & 7)) * LDS + (bg & 1) * 8) * 2);

    float acc[2][2][4];
    #pragma unroll
    for (int i = 0; i < 2; i++)
        #pragma unroll
        for (int j = 0; j < 2; j++)
            #pragma unroll
            for (int v = 0; v < 4; v++) acc[i][j][v] = 0.f;

    const int nchunks = kchunk >> 6;
    for (int c = 0; c < nchunks; c++) {
        const int kc = kbeg + c * 64;
        // ---- stage A and B 64x64 fp32 -> bf16 hi/lo smem ----
        {
            const float* Ap = A + (size_t)(m0 + lr) * lda + kc + lc;
            const float* Bp = B + (size_t)(n0 + lr) * ldb + kc + lc;
            int sIdx = lr * (LDS / 2) + lc / 2;   // bf162 index
            #pragma unroll
            for (int j = 0; j < 4; j++) {
                float4 va = *reinterpret_cast<const float4*>(Ap + j * 4);
                unsigned h0, l0, h1, l1;
                split2(va.x, va.y, h0, l0);
                split2(va.z, va.w, h1, l1);
                sm2[sIdx + j * 2]                    = *reinterpret_cast<__nv_bfloat162*>(&h0);
                sm2[sIdx + j * 2 + 1]                = *reinterpret_cast<__nv_bfloat162*>(&h1);
                sm2[TILE_ELE / 2 + sIdx + j * 2]     = *reinterpret_cast<__nv_bfloat162*>(&l0);
                sm2[TILE_ELE / 2 + sIdx + j * 2 + 1] = *reinterpret_cast<__nv_bfloat162*>(&l1);
            }
            #pragma unroll
            for (int j = 0; j < 4; j++) {
                float4 vb = *reinterpret_cast<const float4*>(Bp + j * 4);
                unsigned h0, l0, h1, l1;
                split2(vb.x, vb.y, h0, l0);
                split2(vb.z, vb.w, h1, l1);
                sm2[2 * TILE_ELE / 2 + sIdx + j * 2]     = *reinterpret_cast<__nv_bfloat162*>(&h0);
                sm2[2 * TILE_ELE / 2 + sIdx + j * 2 + 1] = *reinterpret_cast<__nv_bfloat162*>(&h1);
                sm2[3 * TILE_ELE / 2 + sIdx + j * 2]     = *reinterpret_cast<__nv_bfloat162*>(&l0);
                sm2[3 * TILE_ELE / 2 + sIdx + j * 2 + 1] = *reinterpret_cast<__nv_bfloat162*>(&l1);
            }
        }
        __syncthreads();

        // ---- compute: 4 k-steps of 16 ----
        #pragma unroll
        for (int ks = 0; ks < 4; ks++) {
            uint32_t ah0[4], ah1[4], al0[4], al1[4], bh[4], bl[4];
            const uint32_t kb = (uint32_t)(ks * 32);
            LDSM_X4(ah0[0], ah0[1], ah0[2], ah0[3], AhB + aOff + kb);
            LDSM_X4(ah1[0], ah1[1], ah1[2], ah1[3], AhB + aOff + kb + 16 * LDS * 2);
            LDSM_X4(al0[0], al0[1], al0[2], al0[3], AlB + aOff + kb);
            LDSM_X4(al1[0], al1[1], al1[2], al1[3], AlB + aOff + kb + 16 * LDS * 2);
            LDSM_X4(bh[0], bh[1], bh[2], bh[3], BhB + bOff + kb);
            LDSM_X4(bl[0], bl[1], bl[2], bl[3], BlB + bOff + kb);

            MMA_BF16(acc[0][0], ah0, bh[0], bh[1]);
            MMA_BF16(acc[0][1], ah0, bh[2], bh[3]);
            MMA_BF16(acc[1][0], ah1, bh[0], bh[1]);
            MMA_BF16(acc[1][1], ah1, bh[2], bh[3]);
            MMA_BF16(acc[0][0], ah0, bl[0], bl[1]);
            MMA_BF16(acc[0][1], ah0, bl[2], bl[3]);
            MMA_BF16(acc[1][0], ah1, bl[0], bl[1]);
            MMA_BF16(acc[1][1], ah1, bl[2], bl[3]);
            MMA_BF16(acc[0][0], al0, bh[0], bh[1]);
            MMA_BF16(acc[0][1], al0, bh[2], bh[3]);
            MMA_BF16(acc[1][0], al1, bh[0], bh[1]);
            MMA_BF16(acc[1][1], al1, bh[2], bh[3]);
        }
        __syncthreads();
    }

    // ---- epilogue ----
    const int rbase = m0 + wy * 32 + (lane >> 2);
    const int cbase = n0 + wx * 16 + (lane & 3) * 2;
    #pragma unroll
    for (int mi = 0; mi < 2; mi++) {
        #pragma unroll
        for (int ni = 0; ni < 2; ni++) {
            int cc = cbase + ni * 8;
            int r0 = rbase + mi * 16;
            float2 v0, v1;
            v0.x = epi(acc[mi][ni][0], r0,     cc,     mode, b1, b2, add, ldadd);
            v0.y = epi(acc[mi][ni][1], r0,     cc + 1, mode, b1, b2, add, ldadd);
            v1.x = epi(acc[mi][ni][2], r0 + 8, cc,     mode, b1, b2, add, ldadd);
            v1.y = epi(acc[mi][ni][3], r0 + 8, cc + 1, mode, b1, b2, add, ldadd);
            *reinterpret_cast<float2*>(&C[(size_t)r0 * ldc + cc])       = v0;
            *reinterpret_cast<float2*>(&C[(size_t)(r0 + 8) * ldc + cc]) = v1;
        }
    }
}

// =================== non-GEMM kernels ===================
__device__ __forceinline__ float sigm(float x) { return 1.0f / (1.0f + expf(-x)); }

__device__ __forceinline__ float bsum(float v, float* sm, int nw) {
    #pragma unroll
    for (int o = 16; o; o >>= 1) v += __shfl_xor_sync(0xffffffffu, v, o);
    int w = threadIdx.x >> 5;
    __syncthreads();
    if ((threadIdx.x & 31) == 0) sm[w] = v;
    __syncthreads();
    float r = 0.f;
    for (int i = 0; i < nw; i++) r += sm[i];
    return r;
}

__global__ __launch_bounds__(256) void gather_sum_kernel(
    const int* __restrict__ rel, const int* __restrict__ ent,
    const float* __restrict__ emb, float* __restrict__ csum)
{
    int b = blockIdx.x;
    int tid = threadIdx.x;
    int warp = tid >> 5, lane = tid & 31;

    __shared__ int sidx[2 * Kn];
    for (int i = tid; i < 2 * Kn; i += 256)
        sidx[i] = (i < Kn) ? rel[b * Kn + i] : ent[b * Kn + (i - Kn)];
    __syncthreads();

    int side = warp >> 2;
    int w    = warp & 3;
    const int* idxs = sidx + side * Kn;

    float4 acc = make_float4(0.f, 0.f, 0.f, 0.f);
    #pragma unroll 4
    for (int k = w; k < Kn; k += 4) {
        int row = idxs[k];
        float4 v = *reinterpret_cast<const float4*>(emb + (size_t)row * Dd + lane * 4);
        acc.x += v.x; acc.y += v.y; acc.z += v.z; acc.w += v.w;
    }

    __shared__ float4 red[8][32];
    red[warp][lane] = acc;
    __syncthreads();
    if ((warp & 3) == 0) {
        float4 s  = red[warp][lane];
        float4 s1 = red[warp + 1][lane];
        float4 s2 = red[warp + 2][lane];
        float4 s3 = red[warp + 3][lane];
        s.x += s1.x + s2.x + s3.x;
        s.y += s1.y + s2.y + s3.y;
        s.z += s1.z + s2.z + s3.z;
        s.w += s1.w + s2.w + s3.w;
        *reinterpret_cast<float4*>(csum + b * D2 + side * Dd + lane * 4) = s;
    }
}

__global__ __launch_bounds__(128) void layernorm_kernel(float* __restrict__ Z,
                                                        const float* __restrict__ a,
                                                        const float* __restrict__ b)
{
    __shared__ float sm[4];
    int row = blockIdx.x, t = threadIdx.x;
    float z = Z[row * Dd + t];
    float mu = bsum(z, sm, 4) * (1.0f / Dd);
    float d = z - mu;
    float var = bsum(d * d, sm, 4) * (1.0f / (Dd - 1));
    float sig = sqrtf(var);
    Z[row * Dd + t] = d / (sig + 1e-3f) * a[t] + b[t];
}

__global__ __launch_bounds__(256) void transpose_sg_kernel(const float* __restrict__ sg,
                                                           float* __restrict__ sgT)
{
    __shared__ float tile[32][33];
    int bx = blockIdx.x;   // along m: 1024/32 = 32
    int by = blockIdx.y;   // along n: 128/32 = 4
    int x = threadIdx.x & 31, y = threadIdx.x >> 5;  // 32x8
    #pragma unroll
    for (int i = 0; i < 32; i += 8)
        tile[y + i][x] = sg[(size_t)(bx * 32 + y + i) * Dd + by * 32 + x];
    __syncthreads();
    #pragma unroll
    for (int i = 0; i < 32; i += 8)
        sgT[(size_t)(by * 32 + y + i) * Bq + bx * 32 + x] = tile[x][y + i];
}

__global__ __launch_bounds__(256) void gather_q_kernel(const int* __restrict__ qry,
                                                       const float* __restrict__ emb,
                                                       float* __restrict__ q)
{
    int idx = blockIdx.x * 256 + threadIdx.x;
    int b = idx >> 7, d = idx & 127;
    q[idx] = emb[(size_t)qry[b] * Dd + d];
}

__global__ __launch_bounds__(256) void lstm_ew_kernel(const float* __restrict__ gates,
                                                      const float* __restrict__ q,
                                                      float* __restrict__ c,
                                                      float* __restrict__ hout,
                                                      float* __restrict__ hr,
                                                      int first)
{
    int b = blockIdx.x, t = threadIdx.x;
    const float* g = gates + (size_t)b * G8;
    float ig = g[t];
    float fg = g[D2 + t];
    float gg = g[2 * D2 + t];
    float cprev = first ? 0.f : c[b * D2 + t];
    float cn = sigm(fg) * cprev + sigm(ig) * tanhf(gg);
    c[b * D2 + t] = cn;
    if (t < Dd) {
        float og = g[3 * D2 + t];
        float h  = sigm(og) * tanhf(cn);
        float ho = q[b * Dd + t] + h;
        hout[b * Dd + t] = ho;
        hr[b * D2 + t]   = ho;
    }
}

__global__ __launch_bounds__(256) void softmax_kernel(float* __restrict__ P)
{
    __shared__ float sm[8];
    __shared__ float ss[8];
    int row = blockIdx.x, t = threadIdx.x;
    float* p = P + (size_t)row * Bq;
    float4 v = *reinterpret_cast<const float4*>(p + t * 4);
    float m = fmaxf(fmaxf(v.x, v.y), fmaxf(v.z, v.w));
    #pragma unroll
    for (int o = 16; o; o >>= 1) m = fmaxf(m, __shfl_xor_sync(0xffffffffu, m, o));
    if ((t & 31) == 0) sm[t >> 5] = m;
    __syncthreads();
    float M = sm[0];
    #pragma unroll
    for (int i = 1; i < 8; i++) M = fmaxf(M, sm[i]);
    float e0 = expf(v.x - M), e1 = expf(v.y - M), e2 = expf(v.z - M), e3 = expf(v.w - M);
    float s = e0 + e1 + e2 + e3;
    #pragma unroll
    for (int o = 16; o; o >>= 1) s += __shfl_xor_sync(0xffffffffu, s, o);
    if ((t & 31) == 0) ss[t >> 5] = s;
    __syncthreads();
    float S = 0.f;
    #pragma unroll
    for (int i = 0; i < 8; i++) S += ss[i];
    float inv = 1.0f / S;
    *reinterpret_cast<float4*>(p + t * 4) = make_float4(e0 * inv, e1 * inv, e2 * inv, e3 * inv);
}

__global__ __launch_bounds__(256) void reduce_r_kernel(const float* __restrict__ part,
                                                       float* __restrict__ hr)
{
    int idx = blockIdx.x * 256 + threadIdx.x;
    int b = idx >> 7, d = idx & 127;
    float s = 0.f;
    #pragma unroll
    for (int z = 0; z < RSPLIT; z++) s += part[(size_t)z * Bq * Dd + idx];
    hr[b * D2 + Dd + d] = s;
}

__global__ __launch_bounds__(128) void cosine_kernel(const float* __restrict__ H,
                                                     const float* __restrict__ G,
                                                     float* __restrict__ out)
{
    __shared__ float sm[4];
    int row = blockIdx.x, t = threadIdx.x;
    float h = H[row * Dd + t];
    float g = G[row * Dd + t];
    float s1 = bsum(h * g, sm, 4);
    float s2 = bsum(h * h, sm, 4);
    float s3 = bsum(g * g, sm, 4);
    if (t == 0) out[row] = s1 / sqrtf(s2 * s3);
}

// =================== launcher ===================
extern "C" void kernel_launch(void* const* d_in, const int* in_sizes, int n_in,
                              void* d_out, int out_size)
{
    const int*   rel = (const int*)d_in[0];
    const int*   ent = (const int*)d_in[1];
    const int*   qry = (const int*)d_in[2];
    const float* emb = (const float*)d_in[3];
    const float* Wg  = (const float*)d_in[4];
    const float* bg  = (const float*)d_in[5];
    const float* p1w = (const float*)d_in[6];
    const float* p1b = (const float*)d_in[7];
    const float* p2w = (const float*)d_in[8];
    const float* p2b = (const float*)d_in[9];
    const float* lna = (const float*)d_in[10];
    const float* lnb = (const float*)d_in[11];
    const float* wih = (const float*)d_in[12];
    const float* whh = (const float*)d_in[13];
    const float* bih = (const float*)d_in[14];
    const float* bhh = (const float*)d_in[15];
    float* out = (float*)d_out;

    float *csum, *support, *hidden, *sg, *sgT, *q, *gq, *gates, *hr, *c, *hout, *logits, *rpart;
    cudaGetSymbolAddress((void**)&csum,    g_csum);
    cudaGetSymbolAddress((void**)&support, g_support);
    cudaGetSymbolAddress((void**)&hidden,  g_hidden);
    cudaGetSymbolAddress((void**)&sg,      g_sg);
    cudaGetSymbolAddress((void**)&sgT,     g_sgT);
    cudaGetSymbolAddress((void**)&q,       g_q);
    cudaGetSymbolAddress((void**)&gq,      g_gq);
    cudaGetSymbolAddress((void**)&gates,   g_gates);
    cudaGetSymbolAddress((void**)&hr,      g_hr);
    cudaGetSymbolAddress((void**)&c,       g_c);
    cudaGetSymbolAddress((void**)&hout,    g_hout);
    cudaGetSymbolAddress((void**)&logits,  g_logits);
    cudaGetSymbolAddress((void**)&rpart,   g_rpart);

    // 1) neighbor gather-sum
    gather_sum_kernel<<<Bq, 256>>>(rel, ent, emb, csum);

    // 2) support = tanh((csum @ Wg^T + 200*bg) / 1024)
    tgemm<<<dim3(2, 16, 1), 256>>>(csum, D2, Wg, D2, support, Dd,
                                   D2, 0, bg, nullptr, nullptr, 0, 1);
    // 3) hidden = relu(support @ p1w^T + p1b)
    tgemm<<<dim3(4, 16, 1), 256>>>(support, Dd, p1w, Dd, hidden, D2,
                                   Dd, 0, p1b, nullptr, nullptr, 0, 2);
    // 4) sg = hidden @ p2w^T + p2b + support ; LN in-place; transpose
    tgemm<<<dim3(2, 16, 1), 256>>>(hidden, D2, p2w, D2, sg, Dd,
                                   D2, 0, p2b, nullptr, support, Dd, 3);
    layernorm_kernel<<<Bq, 128>>>(sg, lna, lnb);
    transpose_sg_kernel<<<dim3(32, 4), 256>>>(sg, sgT);

    // 5) q gather ; gq = q @ wih^T + bih + bhh (first 896 gate cols)
    gather_q_kernel<<<Bq * Dd / 256, 256>>>(qry, emb, q);
    tgemm<<<dim3(14, 16, 1), 256>>>(q, Dd, wih, Dd, gq, G8,
                                    Dd, 0, bih, bhh, nullptr, 0, 4);

    // 6) LSTM + attention loop
    for (int s = 0; s < STEPS; s++) {
        const float* gsrc = gq;
        if (s > 0) {
            tgemm<<<dim3(14, 16, 1), 256>>>(hr, D2, whh, D2, gates, G8,
                                            D2, 0, nullptr, nullptr, gq, G8, 5);
            gsrc = gates;
        }
        lstm_ew_kernel<<<Bq, 256>>>(gsrc, q, c, hout, hr, s == 0 ? 1 : 0);

        // logits = hout @ sg^T ; softmax rows
        tgemm<<<dim3(16, 16, 1), 256>>>(hout, Dd, sg, Dd, logits, Bq,
                                        Dd, 0, nullptr, nullptr, nullptr, 0, 0);
        softmax_kernel<<<Bq, 256>>>(logits);

        // r = P @ sg : split-K over 1024 (z=4, kchunk=256) via sgT (TN form)
        tgemm<<<dim3(2, 16, RSPLIT), 256>>>(logits, Bq, sgT, Bq, rpart, Dd,
                                            Bq / RSPLIT, (long)Bq * Dd,
                                            nullptr, nullptr, nullptr, 0, 0);
        reduce_r_kernel<<<Bq * Dd / 256, 256>>>(rpart, hr);
    }

    // 7) cosine similarity
    cosine_kernel<<<Bq, 128>>>(hout, sg, out);
}

// round 4
// speedup vs baseline: 1.5190x; 1.0015x over previous
#include <cuda_runtime.h>
#include <cuda_bf16.h>
#include <math.h>
#include <stdint.h>

// Problem constants
#define Bq   1024
#define Kn   200
#define Dd   128
#define D2   256
#define G8   1024      // 8*D
#define STEPS 4
#define RSPLIT 4

// ---------------- device scratch ----------------
__device__ float g_csum  [Bq * D2];
__device__ float g_support[Bq * Dd];
__device__ float g_hidden[Bq * D2];
__device__ float g_sg    [Bq * Dd];
__device__ float g_sgT   [Dd * Bq];
__device__ float g_q     [Bq * Dd];
__device__ float g_gq    [Bq * G8];
__device__ float g_gates [Bq * G8];
__device__ float g_hr    [Bq * D2];
__device__ float g_c     [Bq * D2];
__device__ float g_hout  [Bq * Dd];
__device__ float g_logits[Bq * Bq];
__device__ float g_rpart [RSPLIT * Bq * Dd];

// =================== helpers ===================
__device__ __forceinline__ uint32_t smem_u32(const void* p) {
    uint32_t a;
    asm("{ .reg .u64 t; cvta.to.shared.u64 t, %1; cvt.u32.u64 %0, t; }" : "=r"(a) : "l"(p));
    return a;
}

#define LDSM_X4(r0, r1, r2, r3, addr) \
    asm volatile("ldmatrix.sync.aligned.m8n8.x4.shared.b16 {%0,%1,%2,%3}, [%4];" \
        : "=r"(r0), "=r"(r1), "=r"(r2), "=r"(r3) : "r"(addr))

#define MMA_BF16(acc, a, bb0, bb1) \
    asm volatile("mma.sync.aligned.m16n8k16.row.col.f32.bf16.bf16.f32 " \
        "{%0,%1,%2,%3}, {%4,%5,%6,%7}, {%8,%9}, {%0,%1,%2,%3};" \
        : "+f"((acc)[0]), "+f"((acc)[1]), "+f"((acc)[2]), "+f"((acc)[3]) \
        : "r"((a)[0]), "r"((a)[1]), "r"((a)[2]), "r"((a)[3]), "r"(bb0), "r"(bb1))

// split two fp32 into bf16-hi pair + bf16-lo (residual) pair
__device__ __forceinline__ void split2(float x0, float x1, unsigned &h, unsigned &l) {
    __nv_bfloat162 hh = __float22bfloat162_rn(make_float2(x0, x1));
    float2 hf = __bfloat1622float2(hh);
    __nv_bfloat162 ll = __float22bfloat162_rn(make_float2(x0 - hf.x, x1 - hf.y));
    h = *reinterpret_cast<unsigned*>(&hh);
    l = *reinterpret_cast<unsigned*>(&ll);
}

// fused epilogue
__device__ __forceinline__ float epi(float x, int m, int n, int mode,
                                     const float* __restrict__ b1,
                                     const float* __restrict__ b2,
                                     const float* __restrict__ add, int ldadd) {
    if (mode == 1) return tanhf((x + 200.0f * b1[n]) * (1.0f / 1024.0f));
    if (mode == 2) return fmaxf(x + b1[n], 0.0f);
    if (mode == 3) return x + b1[n] + add[(size_t)m * ldadd + n];
    if (mode == 4) return x + b1[n] + b2[n];
    if (mode == 5) return x + add[(size_t)m * ldadd + n];
    return x;
}

// =================== HMMA TN GEMM: C = A(MxK) @ B(NxK)^T, fp32 via bf16x3 =============
// CTA tile 64x64, warps 2x4 (each 32x16), K staged 64 per chunk.
// Software pipelined: register prefetch of chunk c+1 + double-buffered smem.
// grid = (N/64, M/64, zsplit); per z: K range [z*kchunk, (z+1)*kchunk)
#define LDS 72                      // bf16 per smem row (144B, ldmatrix conflict-free)
#define TILE_ELE (64 * LDS)         // 4608 bf16
#define TILE_B   (TILE_ELE * 2)     // 9216 bytes
#define BUF_B    (4 * TILE_B)       // 36864 bytes: Ah|Al|Bh|Bl
#define TG_SMEM  (2 * BUF_B)        // 73728

__global__ void __launch_bounds__(256)
tgemm(const float* __restrict__ A, int lda,
      const float* __restrict__ B, int ldb,
      float* __restrict__ C, int ldc,
      int kchunk, long zstride,
      const float* __restrict__ b1, const float* __restrict__ b2,
      const float* __restrict__ add, int ldadd, int mode)
{
    extern __shared__ __nv_bfloat162 sm2[];   // [2][4][TILE_ELE/2]
    const uint32_t sbase = smem_u32(sm2);

    const int tid  = threadIdx.x;
    const int lane = tid & 31;
    const int wid  = tid >> 5;
    const int wy   = wid >> 2;           // 0..1  (rows of 32)
    const int wx   = wid & 3;            // 0..3  (cols of 16)
    const int m0 = blockIdx.y * 64;
    const int n0 = blockIdx.x * 64;
    const int kbeg = blockIdx.z * kchunk;
    C += (long)blockIdx.z * zstride;

    // loader indexing: row = tid/4 (0..63), col-quad = tid%4 (16 cols each)
    const int lr = tid >> 2;
    const int lc = (tid & 3) * 16;
    const int sIdx = lr * (LDS / 2) + lc / 2;     // bf162 index within a tile

    // ldmatrix source byte-offsets within a buffer
    const uint32_t aOff = (uint32_t)(((wy * 32 + (lane & 15)) * LDS + (lane >> 4) * 8) * 2);
    const int bg = lane >> 3;
    const uint32_t bOff = (uint32_t)(((wx * 16 + (bg >> 1) * 8 + (lane & 7)) * LDS + (bg & 1) * 8) * 2);

    float acc[2][2][4];
    #pragma unroll
    for (int i = 0; i < 2; i++)
        #pragma unroll
        for (int j = 0; j < 2; j++)
            #pragma unroll
            for (int v = 0; v < 4; v++) acc[i][j][v] = 0.f;

    const float* Ap = A + (size_t)(m0 + lr) * lda + kbeg + lc;
    const float* Bp = B + (size_t)(n0 + lr) * ldb + kbeg + lc;

    // prefetch chunk 0
    float4 pa[4], pb[4];
    #pragma unroll
    for (int j = 0; j < 4; j++) {
        pa[j] = *reinterpret_cast<const float4*>(Ap + j * 4);
        pb[j] = *reinterpret_cast<const float4*>(Bp + j * 4);
    }

    const int nchunks = kchunk >> 6;
    for (int c = 0; c < nchunks; c++) {
        const int buf = c & 1;
        __nv_bfloat162* sAh = sm2 + buf * (BUF_B / 4);            // bf162 units
        __nv_bfloat162* sAl = sAh + TILE_ELE / 2;
        __nv_bfloat162* sBh = sAl + TILE_ELE / 2;
        __nv_bfloat162* sBl = sBh + TILE_ELE / 2;

        // split prefetched regs -> smem bf16 hi/lo
        #pragma unroll
        for (int j = 0; j < 4; j++) {
            unsigned h0, l0, h1, l1;
            split2(pa[j].x, pa[j].y, h0, l0);
            split2(pa[j].z, pa[j].w, h1, l1);
            sAh[sIdx + j * 2]     = *reinterpret_cast<__nv_bfloat162*>(&h0);
            sAh[sIdx + j * 2 + 1] = *reinterpret_cast<__nv_bfloat162*>(&h1);
            sAl[sIdx + j * 2]     = *reinterpret_cast<__nv_bfloat162*>(&l0);
            sAl[sIdx + j * 2 + 1] = *reinterpret_cast<__nv_bfloat162*>(&l1);
        }
        #pragma unroll
        for (int j = 0; j < 4; j++) {
            unsigned h0, l0, h1, l1;
            split2(pb[j].x, pb[j].y, h0, l0);
            split2(pb[j].z, pb[j].w, h1, l1);
            sBh[sIdx + j * 2]     = *reinterpret_cast<__nv_bfloat162*>(&h0);
            sBh[sIdx + j * 2 + 1] = *reinterpret_cast<__nv_bfloat162*>(&h1);
            sBl[sIdx + j * 2]     = *reinterpret_cast<__nv_bfloat162*>(&l0);
            sBl[sIdx + j * 2 + 1] = *reinterpret_cast<__nv_bfloat162*>(&l1);
        }

        // issue next chunk's global loads (latency hidden under MMA below)
        if (c + 1 < nchunks) {
            const float* An = Ap + (c + 1) * 64;
            const float* Bn = Bp + (c + 1) * 64;
            #pragma unroll
            for (int j = 0; j < 4; j++) {
                pa[j] = *reinterpret_cast<const float4*>(An + j * 4);
                pb[j] = *reinterpret_cast<const float4*>(Bn + j * 4);
            }
        }
        __syncthreads();

        const uint32_t base = sbase + (uint32_t)buf * BUF_B;
        const uint32_t AhB = base, AlB = base + TILE_B, BhB = base + 2 * TILE_B, BlB = base + 3 * TILE_B;

        #pragma unroll
        for (int ks = 0; ks < 4; ks++) {
            uint32_t ah0[4], ah1[4], al0[4], al1[4], bh[4], bl[4];
            const uint32_t kb = (uint32_t)(ks * 32);
            LDSM_X4(ah0[0], ah0[1], ah0[2], ah0[3], AhB + aOff + kb);
            LDSM_X4(ah1[0], ah1[1], ah1[2], ah1[3], AhB + aOff + kb + 16 * LDS * 2);
            LDSM_X4(al0[0], al0[1], al0[2], al0[3], AlB + aOff + kb);
            LDSM_X4(al1[0], al1[1], al1[2], al1[3], AlB + aOff + kb + 16 * LDS * 2);
            LDSM_X4(bh[0], bh[1], bh[2], bh[3], BhB + bOff + kb);
            LDSM_X4(bl[0], bl[1], bl[2], bl[3], BlB + bOff + kb);

            MMA_BF16(acc[0][0], ah0, bh[0], bh[1]);
            MMA_BF16(acc[0][1], ah0, bh[2], bh[3]);
            MMA_BF16(acc[1][0], ah1, bh[0], bh[1]);
            MMA_BF16(acc[1][1], ah1, bh[2], bh[3]);
            MMA_BF16(acc[0][0], ah0, bl[0], bl[1]);
            MMA_BF16(acc[0][1], ah0, bl[2], bl[3]);
            MMA_BF16(acc[1][0], ah1, bl[0], bl[1]);
            MMA_BF16(acc[1][1], ah1, bl[2], bl[3]);
            MMA_BF16(acc[0][0], al0, bh[0], bh[1]);
            MMA_BF16(acc[0][1], al0, bh[2], bh[3]);
            MMA_BF16(acc[1][0], al1, bh[0], bh[1]);
            MMA_BF16(acc[1][1], al1, bh[2], bh[3]);
        }
        // no trailing sync: next iteration writes the OTHER buffer, and the
        // per-iteration sync orders buffer reuse two iterations apart.
    }

    // ---- epilogue ----
    const int rbase = m0 + wy * 32 + (lane >> 2);
    const int cbase = n0 + wx * 16 + (lane & 3) * 2;
    #pragma unroll
    for (int mi = 0; mi < 2; mi++) {
        #pragma unroll
        for (int ni = 0; ni < 2; ni++) {
            int cc = cbase + ni * 8;
            int r0 = rbase + mi * 16;
            float2 v0, v1;
            v0.x = epi(acc[mi][ni][0], r0,     cc,     mode, b1, b2, add, ldadd);
            v0.y = epi(acc[mi][ni][1], r0,     cc + 1, mode, b1, b2, add, ldadd);
            v1.x = epi(acc[mi][ni][2], r0 + 8, cc,     mode, b1, b2, add, ldadd);
            v1.y = epi(acc[mi][ni][3], r0 + 8, cc + 1, mode, b1, b2, add, ldadd);
            *reinterpret_cast<float2*>(&C[(size_t)r0 * ldc + cc])       = v0;
            *reinterpret_cast<float2*>(&C[(size_t)(r0 + 8) * ldc + cc]) = v1;
        }
    }
}

// =================== non-GEMM kernels ===================
__device__ __forceinline__ float sigm(float x) { return 1.0f / (1.0f + expf(-x)); }

__device__ __forceinline__ float bsum(float v, float* sm, int nw) {
    #pragma unroll
    for (int o = 16; o; o >>= 1) v += __shfl_xor_sync(0xffffffffu, v, o);
    int w = threadIdx.x >> 5;
    __syncthreads();
    if ((threadIdx.x & 31) == 0) sm[w] = v;
    __syncthreads();
    float r = 0.f;
    for (int i = 0; i < nw; i++) r += sm[i];
    return r;
}

__global__ __launch_bounds__(256) void gather_sum_kernel(
    const int* __restrict__ rel, const int* __restrict__ ent,
    const float* __restrict__ emb, float* __restrict__ csum)
{
    int b = blockIdx.x;
    int tid = threadIdx.x;
    int warp = tid >> 5, lane = tid & 31;

    __shared__ int sidx[2 * Kn];
    for (int i = tid; i < 2 * Kn; i += 256)
        sidx[i] = (i < Kn) ? rel[b * Kn + i] : ent[b * Kn + (i - Kn)];
    __syncthreads();

    int side = warp >> 2;
    int w    = warp & 3;
    const int* idxs = sidx + side * Kn;

    float4 acc = make_float4(0.f, 0.f, 0.f, 0.f);
    #pragma unroll 4
    for (int k = w; k < Kn; k += 4) {
        int row = idxs[k];
        float4 v = *reinterpret_cast<const float4*>(emb + (size_t)row * Dd + lane * 4);
        acc.x += v.x; acc.y += v.y; acc.z += v.z; acc.w += v.w;
    }

    __shared__ float4 red[8][32];
    red[warp][lane] = acc;
    __syncthreads();
    if ((warp & 3) == 0) {
        float4 s  = red[warp][lane];
        float4 s1 = red[warp + 1][lane];
        float4 s2 = red[warp + 2][lane];
        float4 s3 = red[warp + 3][lane];
        s.x += s1.x + s2.x + s3.x;
        s.y += s1.y + s2.y + s3.y;
        s.z += s1.z + s2.z + s3.z;
        s.w += s1.w + s2.w + s3.w;
        *reinterpret_cast<float4*>(csum + b * D2 + side * Dd + lane * 4) = s;
    }
}

__global__ __launch_bounds__(128) void layernorm_kernel(float* __restrict__ Z,
                                                        const float* __restrict__ a,
                                                        const float* __restrict__ b)
{
    __shared__ float sm[4];
    int row = blockIdx.x, t = threadIdx.x;
    float z = Z[row * Dd + t];
    float mu = bsum(z, sm, 4) * (1.0f / Dd);
    float d = z - mu;
    float var = bsum(d * d, sm, 4) * (1.0f / (Dd - 1));
    float sig = sqrtf(var);
    Z[row * Dd + t] = d / (sig + 1e-3f) * a[t] + b[t];
}

__global__ __launch_bounds__(256) void transpose_sg_kernel(const float* __restrict__ sg,
                                                           float* __restrict__ sgT)
{
    __shared__ float tile[32][33];
    int bx = blockIdx.x;
    int by = blockIdx.y;
    int x = threadIdx.x & 31, y = threadIdx.x >> 5;
    #pragma unroll
    for (int i = 0; i < 32; i += 8)
        tile[y + i][x] = sg[(size_t)(bx * 32 + y + i) * Dd + by * 32 + x];
    __syncthreads();
    #pragma unroll
    for (int i = 0; i < 32; i += 8)
        sgT[(size_t)(by * 32 + y + i) * Bq + bx * 32 + x] = tile[x][y + i];
}

__global__ __launch_bounds__(256) void gather_q_kernel(const int* __restrict__ qry,
                                                       const float* __restrict__ emb,
                                                       float* __restrict__ q)
{
    int idx = blockIdx.x * 256 + threadIdx.x;
    int b = idx >> 7, d = idx & 127;
    q[idx] = emb[(size_t)qry[b] * Dd + d];
}

__global__ __launch_bounds__(256) void lstm_ew_kernel(const float* __restrict__ gates,
                                                      const float* __restrict__ q,
                                                      float* __restrict__ c,
                                                      float* __restrict__ hout,
                                                      float* __restrict__ hr,
                                                      int first)
{
    int b = blockIdx.x, t = threadIdx.x;
    const float* g = gates + (size_t)b * G8;
    float ig = g[t];
    float fg = g[D2 + t];
    float gg = g[2 * D2 + t];
    float cprev = first ? 0.f : c[b * D2 + t];
    float cn = sigm(fg) * cprev + sigm(ig) * tanhf(gg);
    c[b * D2 + t] = cn;
    if (t < Dd) {
        float og = g[3 * D2 + t];
        float h  = sigm(og) * tanhf(cn);
        float ho = q[b * Dd + t] + h;
        hout[b * Dd + t] = ho;
        hr[b * D2 + t]   = ho;
    }
}

__global__ __launch_bounds__(256) void softmax_kernel(float* __restrict__ P)
{
    __shared__ float sm[8];
    __shared__ float ss[8];
    int row = blockIdx.x, t = threadIdx.x;
    float* p = P + (size_t)row * Bq;
    float4 v = *reinterpret_cast<const float4*>(p + t * 4);
    float m = fmaxf(fmaxf(v.x, v.y), fmaxf(v.z, v.w));
    #pragma unroll
    for (int o = 16; o; o >>= 1) m = fmaxf(m, __shfl_xor_sync(0xffffffffu, m, o));
    if ((t & 31) == 0) sm[t >> 5] = m;
    __syncthreads();
    float M = sm[0];
    #pragma unroll
    for (int i = 1; i < 8; i++) M = fmaxf(M, sm[i]);
    float e0 = expf(v.x - M), e1 = expf(v.y - M), e2 = expf(v.z - M), e3 = expf(v.w - M);
    float s = e0 + e1 + e2 + e3;
    #pragma unroll
    for (int o = 16; o; o >>= 1) s += __shfl_xor_sync(0xffffffffu, s, o);
    if ((t & 31) == 0) ss[t >> 5] = s;
    __syncthreads();
    float S = 0.f;
    #pragma unroll
    for (int i = 0; i < 8; i++) S += ss[i];
    float inv = 1.0f / S;
    *reinterpret_cast<float4*>(p + t * 4) = make_float4(e0 * inv, e1 * inv, e2 * inv, e3 * inv);
}

__global__ __launch_bounds__(256) void reduce_r_kernel(const float* __restrict__ part,
                                                       float* __restrict__ hr)
{
    int idx = blockIdx.x * 256 + threadIdx.x;
    int b = idx >> 7, d = idx & 127;
    float s = 0.f;
    #pragma unroll
    for (int z = 0; z < RSPLIT; z++) s += part[(size_t)z * Bq * Dd + idx];
    hr[b * D2 + Dd + d] = s;
}

__global__ __launch_bounds__(128) void cosine_kernel(const float* __restrict__ H,
                                                     const float* __restrict__ G,
                                                     float* __restrict__ out)
{
    __shared__ float sm[4];
    int row = blockIdx.x, t = threadIdx.x;
    float h = H[row * Dd + t];
    float g = G[row * Dd + t];
    float s1 = bsum(h * g, sm, 4);
    float s2 = bsum(h * h, sm, 4);
    float s3 = bsum(g * g, sm, 4);
    if (t == 0) out[row] = s1 / sqrtf(s2 * s3);
}

// =================== launcher ===================
extern "C" void kernel_launch(void* const* d_in, const int* in_sizes, int n_in,
                              void* d_out, int out_size)
{
    const int*   rel = (const int*)d_in[0];
    const int*   ent = (const int*)d_in[1];
    const int*   qry = (const int*)d_in[2];
    const float* emb = (const float*)d_in[3];
    const float* Wg  = (const float*)d_in[4];
    const float* bg  = (const float*)d_in[5];
    const float* p1w = (const float*)d_in[6];
    const float* p1b = (const float*)d_in[7];
    const float* p2w = (const float*)d_in[8];
    const float* p2b = (const float*)d_in[9];
    const float* lna = (const float*)d_in[10];
    const float* lnb = (const float*)d_in[11];
    const float* wih = (const float*)d_in[12];
    const float* whh = (const float*)d_in[13];
    const float* bih = (const float*)d_in[14];
    const float* bhh = (const float*)d_in[15];
    float* out = (float*)d_out;

    float *csum, *support, *hidden, *sg, *sgT, *q, *gq, *gates, *hr, *c, *hout, *logits, *rpart;
    cudaGetSymbolAddress((void**)&csum,    g_csum);
    cudaGetSymbolAddress((void**)&support, g_support);
    cudaGetSymbolAddress((void**)&hidden,  g_hidden);
    cudaGetSymbolAddress((void**)&sg,      g_sg);
    cudaGetSymbolAddress((void**)&sgT,     g_sgT);
    cudaGetSymbolAddress((void**)&q,       g_q);
    cudaGetSymbolAddress((void**)&gq,      g_gq);
    cudaGetSymbolAddress((void**)&gates,   g_gates);
    cudaGetSymbolAddress((void**)&hr,      g_hr);
    cudaGetSymbolAddress((void**)&c,       g_c);
    cudaGetSymbolAddress((void**)&hout,    g_hout);
    cudaGetSymbolAddress((void**)&logits,  g_logits);
    cudaGetSymbolAddress((void**)&rpart,   g_rpart);

    cudaFuncSetAttribute(tgemm, cudaFuncAttributeMaxDynamicSharedMemorySize, TG_SMEM);

    // 1) neighbor gather-sum
    gather_sum_kernel<<<Bq, 256>>>(rel, ent, emb, csum);

    // 2) support = tanh((csum @ Wg^T + 200*bg) / 1024)
    tgemm<<<dim3(2, 16, 1), 256, TG_SMEM>>>(csum, D2, Wg, D2, support, Dd,
                                            D2, 0, bg, nullptr, nullptr, 0, 1);
    // 3) hidden = relu(support @ p1w^T + p1b)
    tgemm<<<dim3(4, 16, 1), 256, TG_SMEM>>>(support, Dd, p1w, Dd, hidden, D2,
                                            Dd, 0, p1b, nullptr, nullptr, 0, 2);
    // 4) sg = hidden @ p2w^T + p2b + support ; LN in-place; transpose
    tgemm<<<dim3(2, 16, 1), 256, TG_SMEM>>>(hidden, D2, p2w, D2, sg, Dd,
                                            D2, 0, p2b, nullptr, support, Dd, 3);
    layernorm_kernel<<<Bq, 128>>>(sg, lna, lnb);
    transpose_sg_kernel<<<dim3(32, 4), 256>>>(sg, sgT);

    // 5) q gather ; gq = q @ wih^T + bih + bhh (first 896 gate cols)
    gather_q_kernel<<<Bq * Dd / 256, 256>>>(qry, emb, q);
    tgemm<<<dim3(14, 16, 1), 256, TG_SMEM>>>(q, Dd, wih, Dd, gq, G8,
                                             Dd, 0, bih, bhh, nullptr, 0, 4);

    // 6) LSTM + attention loop
    for (int s = 0; s < STEPS; s++) {
        const float* gsrc = gq;
        if (s > 0) {
            tgemm<<<dim3(14, 16, 1), 256, TG_SMEM>>>(hr, D2, whh, D2, gates, G8,
                                                     D2, 0, nullptr, nullptr, gq, G8, 5);
            gsrc = gates;
        }
        lstm_ew_kernel<<<Bq, 256>>>(gsrc, q, c, hout, hr, s == 0 ? 1 : 0);

        // logits = hout @ sg^T ; softmax rows
        tgemm<<<dim3(16, 16, 1), 256, TG_SMEM>>>(hout, Dd, sg, Dd, logits, Bq,
                                                 Dd, 0, nullptr, nullptr, nullptr, 0, 0);
        softmax_kernel<<<Bq, 256>>>(logits);

        // r = P @ sg : split-K over 1024 (z=4, kchunk=256) via sgT (TN form)
        tgemm<<<dim3(2, 16, RSPLIT), 256, TG_SMEM>>>(logits, Bq, sgT, Bq, rpart, Dd,
                                                     Bq / RSPLIT, (long)Bq * Dd,
                                                     nullptr, nullptr, nullptr, 0, 0);
        reduce_r_kernel<<<Bq * Dd / 256, 256>>>(rpart, hr);
    }

    // 7) cosine similarity
    cosine_kernel<<<Bq, 128>>>(hout, sg, out);
}